// round 8
// baseline (speedup 1.0000x reference)
#include <cuda_runtime.h>
#include <cuda_fp16.h>

// Problem-fixed shapes
#define NN 262144
#define EE 4194304
#define BN_EPS 1e-5f

// ---------------- scratch (static device globals; no allocation) ----------------
__device__ float  d_deg[NN];
__device__ float  d_dinv[NN];
__device__ __half d_gx[NN];       // f16: dinv[i] * x[i]          (512 KB)
__device__ float  d_agg1[NN];     // f32 accumulators
__device__ __half d_g2[NN * 4];   // f16 half4 per node           (2 MB)
__device__ float4 d_agg2[NN];
__device__ __half d_g3[NN];       // f16                          (512 KB)
__device__ float  d_agg3[NN];

// folded per-layer affine params
__device__ float d_a1[16], d_c1[16];   // layer1: relu(t*a1 + c1)
__device__ float d_W2v[64];            // [16,4] row-major
__device__ float d_s2[4], d_c2[4];     // layer2 bn fold
__device__ float d_W3v[4];
__device__ float d_za, d_zc;           // final: sigmoid(agg3*dinv*za + zc)

// 16B vector reduction (sm_90+)
__device__ __forceinline__ void red_add_v4(float4* addr, float a, float b, float c, float d) {
    asm volatile("red.global.add.v4.f32 [%0], {%1, %2, %3, %4};"
                 :: "l"(addr), "f"(a), "f"(b), "f"(c), "f"(d) : "memory");
}

// evict-first streaming loads (single-use data; don't churn L2)
__device__ __forceinline__ int4 ldcs_int4(const int4* p) {
    int4 v;
    asm volatile("ld.global.cs.v4.s32 {%0,%1,%2,%3}, [%4];"
                 : "=r"(v.x), "=r"(v.y), "=r"(v.z), "=r"(v.w) : "l"(p));
    return v;
}
__device__ __forceinline__ float4 ldcs_float4(const float4* p) {
    float4 v;
    asm volatile("ld.global.cs.v4.f32 {%0,%1,%2,%3}, [%4];"
                 : "=f"(v.x), "=f"(v.y), "=f"(v.z), "=f"(v.w) : "l"(p));
    return v;
}

// ---------------- kernels ----------------

// fused: init deg to self-loop weight 1.0; block 0 also folds the affine params
__global__ void k_init(const float* __restrict__ W1, const float* __restrict__ b1,
                       const float* __restrict__ W2, const float* __restrict__ b2,
                       const float* __restrict__ W3, const float* __restrict__ b3,
                       const float* __restrict__ g1, const float* __restrict__ be1,
                       const float* __restrict__ m1, const float* __restrict__ v1,
                       const float* __restrict__ g2, const float* __restrict__ be2,
                       const float* __restrict__ m2, const float* __restrict__ v2,
                       const float* __restrict__ We, const float* __restrict__ bee) {
    int i = blockIdx.x * blockDim.x + threadIdx.x;
    if (i < NN) d_deg[i] = 1.0f;
    if (blockIdx.x == 0) {
        int t = threadIdx.x;
        if (t < 16) {
            float s = g1[t] * rsqrtf(v1[t] + BN_EPS);
            d_a1[t] = W1[t] * s;
            d_c1[t] = (b1[t] - m1[t]) * s + be1[t];
        }
        if (t < 64) d_W2v[t] = W2[t];
        if (t < 4) {
            float s = g2[t] * rsqrtf(v2[t] + BN_EPS);
            d_s2[t] = s;
            d_c2[t] = (b2[t] - m2[t]) * s + be2[t];
            d_W3v[t] = W3[t];
        }
        if (t == 0) { d_za = We[0]; d_zc = b3[0] * We[0] + bee[0]; }
    }
}

// degree accumulation: 16 edges/thread, streaming loads
__global__ void k_deg(const int* __restrict__ ei, const float* __restrict__ ew) {
    int t = blockIdx.x * blockDim.x + threadIdx.x;   // t < EE/16
    if (t < EE / 16) {
#pragma unroll
        for (int r = 0; r < 4; r++) {
            int4   dd = ldcs_int4(((const int4*)(ei + EE)) + 4 * t + r);
            float4 w  = ldcs_float4(((const float4*)ew) + 4 * t + r);
            atomicAdd(&d_deg[dd.x], w.x);
            atomicAdd(&d_deg[dd.y], w.y);
            atomicAdd(&d_deg[dd.z], w.z);
            atomicAdd(&d_deg[dd.w], w.w);
        }
    }
}

// dinv, gx = dinv*x (f16), agg1 init = gx (f32)
__global__ void k_dinv(const float* __restrict__ x) {
    int i = blockIdx.x * blockDim.x + threadIdx.x;
    if (i < NN) {
        float di = rsqrtf(d_deg[i]);
        d_dinv[i] = di;
        float g = x[i] * di;
        d_gx[i] = __float2half(g);
        d_agg1[i] = g;
    }
}

// edge pass 1: agg1[d] += w * gx[s]  (one 2B gather + one f32 atomic per edge)
__global__ void k_e1(const int* __restrict__ ei, const float* __restrict__ ew) {
    int t = blockIdx.x * blockDim.x + threadIdx.x;   // t < EE/16
    if (t < EE / 16) {
#pragma unroll
        for (int r = 0; r < 4; r++) {
            int4   ss = ldcs_int4(((const int4*)ei) + 4 * t + r);
            int4   dd = ldcs_int4(((const int4*)(ei + EE)) + 4 * t + r);
            float4 w  = ldcs_float4(((const float4*)ew) + 4 * t + r);
            atomicAdd(&d_agg1[dd.x], w.x * __half2float(__ldg(&d_gx[ss.x])));
            atomicAdd(&d_agg1[dd.y], w.y * __half2float(__ldg(&d_gx[ss.y])));
            atomicAdd(&d_agg1[dd.z], w.z * __half2float(__ldg(&d_gx[ss.z])));
            atomicAdd(&d_agg1[dd.w], w.w * __half2float(__ldg(&d_gx[ss.w])));
        }
    }
}

// node pass 1: t = dinv*agg1; folded bn+relu -> W2 -> h2; g2 = dinv*h2 (half4); agg2 init
__global__ void k_n1() {
    int i = blockIdx.x * blockDim.x + threadIdx.x;
    if (i < NN) {
        float di = d_dinv[i];
        float t = di * d_agg1[i];
        float a0 = 0.f, a1 = 0.f, a2 = 0.f, a3 = 0.f;
#pragma unroll
        for (int j = 0; j < 16; j++) {
            float p = fmaxf(fmaf(t, d_a1[j], d_c1[j]), 0.f);
            a0 = fmaf(p, d_W2v[j * 4 + 0], a0);
            a1 = fmaf(p, d_W2v[j * 4 + 1], a1);
            a2 = fmaf(p, d_W2v[j * 4 + 2], a2);
            a3 = fmaf(p, d_W2v[j * 4 + 3], a3);
        }
        float4 g = make_float4(a0 * di, a1 * di, a2 * di, a3 * di);
        __half2 h01 = __floats2half2_rn(g.x, g.y);
        __half2 h23 = __floats2half2_rn(g.z, g.w);
        uint2 pk;
        pk.x = *(unsigned int*)&h01;
        pk.y = *(unsigned int*)&h23;
        ((uint2*)d_g2)[i] = pk;
        d_agg2[i] = g;
    }
}

__device__ __forceinline__ float4 ldg_half4(int idx) {
    uint2 pk = __ldg(&((const uint2*)d_g2)[idx]);
    __half2 h01 = *(__half2*)&pk.x;
    __half2 h23 = *(__half2*)&pk.y;
    float2 f01 = __half22float2(h01);
    float2 f23 = __half22float2(h23);
    return make_float4(f01.x, f01.y, f23.x, f23.y);
}

// edge pass 2: agg2[d] += w * g2[s]  (8B gather + 16B vector reduction; 16 edges/thread)
__global__ void k_e2(const int* __restrict__ ei, const float* __restrict__ ew) {
    int t = blockIdx.x * blockDim.x + threadIdx.x;   // t < EE/16
    if (t < EE / 16) {
#pragma unroll
        for (int r = 0; r < 4; r++) {
            int4   ss = ldcs_int4(((const int4*)ei) + 4 * t + r);
            int4   dd = ldcs_int4(((const int4*)(ei + EE)) + 4 * t + r);
            float4 w  = ldcs_float4(((const float4*)ew) + 4 * t + r);
            float4 h;
            h = ldg_half4(ss.x); red_add_v4(&d_agg2[dd.x], w.x * h.x, w.x * h.y, w.x * h.z, w.x * h.w);
            h = ldg_half4(ss.y); red_add_v4(&d_agg2[dd.y], w.y * h.x, w.y * h.y, w.y * h.z, w.y * h.w);
            h = ldg_half4(ss.z); red_add_v4(&d_agg2[dd.z], w.z * h.x, w.z * h.y, w.z * h.z, w.z * h.w);
            h = ldg_half4(ss.w); red_add_v4(&d_agg2[dd.w], w.w * h.x, w.w * h.y, w.w * h.z, w.w * h.w);
        }
    }
}

// node pass 2: v = dinv*agg2; folded bn+relu -> W3 -> h3; g3 = dinv*h3 (f16); agg3 init
__global__ void k_n2() {
    int i = blockIdx.x * blockDim.x + threadIdx.x;
    if (i < NN) {
        float di = d_dinv[i];
        float4 v = d_agg2[i];
        float h3 = 0.f;
        float q;
        q = fmaxf(fmaf(di * v.x, d_s2[0], d_c2[0]), 0.f); h3 = fmaf(q, d_W3v[0], h3);
        q = fmaxf(fmaf(di * v.y, d_s2[1], d_c2[1]), 0.f); h3 = fmaf(q, d_W3v[1], h3);
        q = fmaxf(fmaf(di * v.z, d_s2[2], d_c2[2]), 0.f); h3 = fmaf(q, d_W3v[2], h3);
        q = fmaxf(fmaf(di * v.w, d_s2[3], d_c2[3]), 0.f); h3 = fmaf(q, d_W3v[3], h3);
        float g = h3 * di;
        d_g3[i] = __float2half(g);
        d_agg3[i] = g;
    }
}

// edge pass 3: agg3[d] += w * g3[s]
__global__ void k_e3(const int* __restrict__ ei, const float* __restrict__ ew) {
    int t = blockIdx.x * blockDim.x + threadIdx.x;   // t < EE/16
    if (t < EE / 16) {
#pragma unroll
        for (int r = 0; r < 4; r++) {
            int4   ss = ldcs_int4(((const int4*)ei) + 4 * t + r);
            int4   dd = ldcs_int4(((const int4*)(ei + EE)) + 4 * t + r);
            float4 w  = ldcs_float4(((const float4*)ew) + 4 * t + r);
            atomicAdd(&d_agg3[dd.x], w.x * __half2float(__ldg(&d_g3[ss.x])));
            atomicAdd(&d_agg3[dd.y], w.y * __half2float(__ldg(&d_g3[ss.y])));
            atomicAdd(&d_agg3[dd.z], w.z * __half2float(__ldg(&d_g3[ss.z])));
            atomicAdd(&d_agg3[dd.w], w.w * __half2float(__ldg(&d_g3[ss.w])));
        }
    }
}

// final: sigmoid(dinv*agg3*za + zc)
__global__ void k_out(float* __restrict__ out) {
    int i = blockIdx.x * blockDim.x + threadIdx.x;
    if (i < NN) {
        float z = fmaf(d_dinv[i] * d_agg3[i], d_za, d_zc);
        out[i] = 1.0f / (1.0f + __expf(-z));
    }
}

// ---------------- launch ----------------
extern "C" void kernel_launch(void* const* d_in, const int* in_sizes, int n_in,
                              void* d_out, int out_size) {
    const float* x   = (const float*)d_in[0];
    const int*   ei  = (const int*)d_in[1];      // int32 [2, E]
    const float* ew  = (const float*)d_in[2];
    const float* W1  = (const float*)d_in[3];
    const float* b1  = (const float*)d_in[4];
    const float* W2  = (const float*)d_in[5];
    const float* b2  = (const float*)d_in[6];
    const float* W3  = (const float*)d_in[7];
    const float* b3  = (const float*)d_in[8];
    const float* g1  = (const float*)d_in[9];
    const float* be1 = (const float*)d_in[10];
    const float* m1  = (const float*)d_in[11];
    const float* v1  = (const float*)d_in[12];
    const float* g2  = (const float*)d_in[13];
    const float* be2 = (const float*)d_in[14];
    const float* m2  = (const float*)d_in[15];
    const float* v2  = (const float*)d_in[16];
    const float* We  = (const float*)d_in[17];
    const float* bee = (const float*)d_in[18];

    const int TB = 256;
    const int NB_N   = NN / TB;         // 1024
    const int NB_E16 = EE / 16 / TB;    // 1024

    k_init<<<NB_N, TB>>>(W1, b1, W2, b2, W3, b3, g1, be1, m1, v1, g2, be2, m2, v2, We, bee);
    k_deg<<<NB_E16, TB>>>(ei, ew);
    k_dinv<<<NB_N, TB>>>(x);
    k_e1<<<NB_E16, TB>>>(ei, ew);
    k_n1<<<NB_N, TB>>>();
    k_e2<<<NB_E16, TB>>>(ei, ew);
    k_n2<<<NB_N, TB>>>();
    k_e3<<<NB_E16, TB>>>(ei, ew);
    k_out<<<NB_N, TB>>>((float*)d_out);
}

// round 9
// speedup vs baseline: 1.0837x; 1.0837x over previous
#include <cuda_runtime.h>
#include <cuda_fp16.h>

// Problem-fixed shapes
#define NN 262144
#define EE 4194304
#define BN_EPS 1e-5f

// ---------------- scratch (static device globals; no allocation) ----------------
__device__ float  d_deg[NN];
__device__ float  d_dinv[NN];
__device__ __half d_gx[NN];       // f16: dinv[i] * x[i]          (512 KB)
__device__ float  d_agg1[NN];     // f32 accumulators
__device__ __half d_g2[NN * 4];   // f16 half4 per node           (2 MB)
__device__ float4 d_agg2[NN];
__device__ __half d_g3[NN];       // f16                          (512 KB)
__device__ float  d_agg3[NN];

// folded per-layer affine params
__device__ float d_a1[16], d_c1[16];   // layer1: relu(t*a1 + c1)
__device__ float d_W2v[64];            // [16,4] row-major
__device__ float d_s2[4], d_c2[4];     // layer2 bn fold
__device__ float d_W3v[4];
__device__ float d_za, d_zc;           // final: sigmoid(agg3*dinv*za + zc)

// 16B vector reduction (sm_90+)
__device__ __forceinline__ void red_add_v4(float4* addr, float a, float b, float c, float d) {
    asm volatile("red.global.add.v4.f32 [%0], {%1, %2, %3, %4};"
                 :: "l"(addr), "f"(a), "f"(b), "f"(c), "f"(d) : "memory");
}

// ---------------- kernels ----------------

// fused: init deg to self-loop weight 1.0; block 0 also folds the affine params
__global__ void k_init(const float* __restrict__ W1, const float* __restrict__ b1,
                       const float* __restrict__ W2, const float* __restrict__ b2,
                       const float* __restrict__ W3, const float* __restrict__ b3,
                       const float* __restrict__ g1, const float* __restrict__ be1,
                       const float* __restrict__ m1, const float* __restrict__ v1,
                       const float* __restrict__ g2, const float* __restrict__ be2,
                       const float* __restrict__ m2, const float* __restrict__ v2,
                       const float* __restrict__ We, const float* __restrict__ bee) {
    int i = blockIdx.x * blockDim.x + threadIdx.x;
    if (i < NN) d_deg[i] = 1.0f;
    if (blockIdx.x == 0) {
        int t = threadIdx.x;
        if (t < 16) {
            float s = g1[t] * rsqrtf(v1[t] + BN_EPS);
            d_a1[t] = W1[t] * s;
            d_c1[t] = (b1[t] - m1[t]) * s + be1[t];
        }
        if (t < 64) d_W2v[t] = W2[t];
        if (t < 4) {
            float s = g2[t] * rsqrtf(v2[t] + BN_EPS);
            d_s2[t] = s;
            d_c2[t] = (b2[t] - m2[t]) * s + be2[t];
            d_W3v[t] = W3[t];
        }
        if (t == 0) { d_za = We[0]; d_zc = b3[0] * We[0] + bee[0]; }
    }
}

// degree accumulation: 8 edges/thread
__global__ void k_deg(const int* __restrict__ ei, const float* __restrict__ ew) {
    int t = blockIdx.x * blockDim.x + threadIdx.x;   // t < EE/8
    if (t < EE / 8) {
        int4   dd0 = ((const int4*)(ei + EE))[2 * t + 0];
        int4   dd1 = ((const int4*)(ei + EE))[2 * t + 1];
        float4 w0  = ((const float4*)ew)[2 * t + 0];
        float4 w1  = ((const float4*)ew)[2 * t + 1];
        atomicAdd(&d_deg[dd0.x], w0.x);
        atomicAdd(&d_deg[dd0.y], w0.y);
        atomicAdd(&d_deg[dd0.z], w0.z);
        atomicAdd(&d_deg[dd0.w], w0.w);
        atomicAdd(&d_deg[dd1.x], w1.x);
        atomicAdd(&d_deg[dd1.y], w1.y);
        atomicAdd(&d_deg[dd1.z], w1.z);
        atomicAdd(&d_deg[dd1.w], w1.w);
    }
}

// dinv, gx = dinv*x (f16), agg1 init = gx (f32)
__global__ void k_dinv(const float* __restrict__ x) {
    int i = blockIdx.x * blockDim.x + threadIdx.x;
    if (i < NN) {
        float di = rsqrtf(d_deg[i]);
        d_dinv[i] = di;
        float g = x[i] * di;
        d_gx[i] = __float2half(g);
        d_agg1[i] = g;
    }
}

// edge pass 1: agg1[d] += w * gx[s]  — front-batch all 8 gathers, then 8 REDs
__global__ void k_e1(const int* __restrict__ ei, const float* __restrict__ ew) {
    int t = blockIdx.x * blockDim.x + threadIdx.x;   // t < EE/8
    if (t < EE / 8) {
        int4   ss0 = ((const int4*)ei)[2 * t + 0];
        int4   ss1 = ((const int4*)ei)[2 * t + 1];
        int4   dd0 = ((const int4*)(ei + EE))[2 * t + 0];
        int4   dd1 = ((const int4*)(ei + EE))[2 * t + 1];
        float4 w0  = ((const float4*)ew)[2 * t + 0];
        float4 w1  = ((const float4*)ew)[2 * t + 1];
        // batch gathers (independent LDGs -> high MLP)
        __half g0 = __ldg(&d_gx[ss0.x]);
        __half g1 = __ldg(&d_gx[ss0.y]);
        __half g2 = __ldg(&d_gx[ss0.z]);
        __half g3 = __ldg(&d_gx[ss0.w]);
        __half g4 = __ldg(&d_gx[ss1.x]);
        __half g5 = __ldg(&d_gx[ss1.y]);
        __half g6 = __ldg(&d_gx[ss1.z]);
        __half g7 = __ldg(&d_gx[ss1.w]);
        atomicAdd(&d_agg1[dd0.x], w0.x * __half2float(g0));
        atomicAdd(&d_agg1[dd0.y], w0.y * __half2float(g1));
        atomicAdd(&d_agg1[dd0.z], w0.z * __half2float(g2));
        atomicAdd(&d_agg1[dd0.w], w0.w * __half2float(g3));
        atomicAdd(&d_agg1[dd1.x], w1.x * __half2float(g4));
        atomicAdd(&d_agg1[dd1.y], w1.y * __half2float(g5));
        atomicAdd(&d_agg1[dd1.z], w1.z * __half2float(g6));
        atomicAdd(&d_agg1[dd1.w], w1.w * __half2float(g7));
    }
}

// node pass 1: t = dinv*agg1; folded bn+relu -> W2 -> h2; g2 = dinv*h2 (half4); agg2 init
__global__ void k_n1() {
    int i = blockIdx.x * blockDim.x + threadIdx.x;
    if (i < NN) {
        float di = d_dinv[i];
        float t = di * d_agg1[i];
        float a0 = 0.f, a1 = 0.f, a2 = 0.f, a3 = 0.f;
#pragma unroll
        for (int j = 0; j < 16; j++) {
            float p = fmaxf(fmaf(t, d_a1[j], d_c1[j]), 0.f);
            a0 = fmaf(p, d_W2v[j * 4 + 0], a0);
            a1 = fmaf(p, d_W2v[j * 4 + 1], a1);
            a2 = fmaf(p, d_W2v[j * 4 + 2], a2);
            a3 = fmaf(p, d_W2v[j * 4 + 3], a3);
        }
        float4 g = make_float4(a0 * di, a1 * di, a2 * di, a3 * di);
        __half2 h01 = __floats2half2_rn(g.x, g.y);
        __half2 h23 = __floats2half2_rn(g.z, g.w);
        uint2 pk;
        pk.x = *(unsigned int*)&h01;
        pk.y = *(unsigned int*)&h23;
        ((uint2*)d_g2)[i] = pk;
        d_agg2[i] = g;
    }
}

__device__ __forceinline__ float4 unpack_half4(uint2 pk) {
    __half2 h01 = *(__half2*)&pk.x;
    __half2 h23 = *(__half2*)&pk.y;
    float2 f01 = __half22float2(h01);
    float2 f23 = __half22float2(h23);
    return make_float4(f01.x, f01.y, f23.x, f23.y);
}

// edge pass 2: agg2[d] += w * g2[s]  — front-batch 8 gathers, then 8 v4 REDs
__global__ void k_e2(const int* __restrict__ ei, const float* __restrict__ ew) {
    int t = blockIdx.x * blockDim.x + threadIdx.x;   // t < EE/8
    if (t < EE / 8) {
        int4   ss0 = ((const int4*)ei)[2 * t + 0];
        int4   ss1 = ((const int4*)ei)[2 * t + 1];
        int4   dd0 = ((const int4*)(ei + EE))[2 * t + 0];
        int4   dd1 = ((const int4*)(ei + EE))[2 * t + 1];
        float4 w0  = ((const float4*)ew)[2 * t + 0];
        float4 w1  = ((const float4*)ew)[2 * t + 1];
        uint2 p0 = __ldg(&((const uint2*)d_g2)[ss0.x]);
        uint2 p1 = __ldg(&((const uint2*)d_g2)[ss0.y]);
        uint2 p2 = __ldg(&((const uint2*)d_g2)[ss0.z]);
        uint2 p3 = __ldg(&((const uint2*)d_g2)[ss0.w]);
        uint2 p4 = __ldg(&((const uint2*)d_g2)[ss1.x]);
        uint2 p5 = __ldg(&((const uint2*)d_g2)[ss1.y]);
        uint2 p6 = __ldg(&((const uint2*)d_g2)[ss1.z]);
        uint2 p7 = __ldg(&((const uint2*)d_g2)[ss1.w]);
        float4 h;
        h = unpack_half4(p0); red_add_v4(&d_agg2[dd0.x], w0.x*h.x, w0.x*h.y, w0.x*h.z, w0.x*h.w);
        h = unpack_half4(p1); red_add_v4(&d_agg2[dd0.y], w0.y*h.x, w0.y*h.y, w0.y*h.z, w0.y*h.w);
        h = unpack_half4(p2); red_add_v4(&d_agg2[dd0.z], w0.z*h.x, w0.z*h.y, w0.z*h.z, w0.z*h.w);
        h = unpack_half4(p3); red_add_v4(&d_agg2[dd0.w], w0.w*h.x, w0.w*h.y, w0.w*h.z, w0.w*h.w);
        h = unpack_half4(p4); red_add_v4(&d_agg2[dd1.x], w1.x*h.x, w1.x*h.y, w1.x*h.z, w1.x*h.w);
        h = unpack_half4(p5); red_add_v4(&d_agg2[dd1.y], w1.y*h.x, w1.y*h.y, w1.y*h.z, w1.y*h.w);
        h = unpack_half4(p6); red_add_v4(&d_agg2[dd1.z], w1.z*h.x, w1.z*h.y, w1.z*h.z, w1.z*h.w);
        h = unpack_half4(p7); red_add_v4(&d_agg2[dd1.w], w1.w*h.x, w1.w*h.y, w1.w*h.z, w1.w*h.w);
    }
}

// node pass 2: v = dinv*agg2; folded bn+relu -> W3 -> h3; g3 = dinv*h3 (f16); agg3 init
__global__ void k_n2() {
    int i = blockIdx.x * blockDim.x + threadIdx.x;
    if (i < NN) {
        float di = d_dinv[i];
        float4 v = d_agg2[i];
        float h3 = 0.f;
        float q;
        q = fmaxf(fmaf(di * v.x, d_s2[0], d_c2[0]), 0.f); h3 = fmaf(q, d_W3v[0], h3);
        q = fmaxf(fmaf(di * v.y, d_s2[1], d_c2[1]), 0.f); h3 = fmaf(q, d_W3v[1], h3);
        q = fmaxf(fmaf(di * v.z, d_s2[2], d_c2[2]), 0.f); h3 = fmaf(q, d_W3v[2], h3);
        q = fmaxf(fmaf(di * v.w, d_s2[3], d_c2[3]), 0.f); h3 = fmaf(q, d_W3v[3], h3);
        float g = h3 * di;
        d_g3[i] = __float2half(g);
        d_agg3[i] = g;
    }
}

// edge pass 3: agg3[d] += w * g3[s]  — front-batch gathers
__global__ void k_e3(const int* __restrict__ ei, const float* __restrict__ ew) {
    int t = blockIdx.x * blockDim.x + threadIdx.x;   // t < EE/8
    if (t < EE / 8) {
        int4   ss0 = ((const int4*)ei)[2 * t + 0];
        int4   ss1 = ((const int4*)ei)[2 * t + 1];
        int4   dd0 = ((const int4*)(ei + EE))[2 * t + 0];
        int4   dd1 = ((const int4*)(ei + EE))[2 * t + 1];
        float4 w0  = ((const float4*)ew)[2 * t + 0];
        float4 w1  = ((const float4*)ew)[2 * t + 1];
        __half g0 = __ldg(&d_g3[ss0.x]);
        __half g1 = __ldg(&d_g3[ss0.y]);
        __half g2 = __ldg(&d_g3[ss0.z]);
        __half g3 = __ldg(&d_g3[ss0.w]);
        __half g4 = __ldg(&d_g3[ss1.x]);
        __half g5 = __ldg(&d_g3[ss1.y]);
        __half g6 = __ldg(&d_g3[ss1.z]);
        __half g7 = __ldg(&d_g3[ss1.w]);
        atomicAdd(&d_agg3[dd0.x], w0.x * __half2float(g0));
        atomicAdd(&d_agg3[dd0.y], w0.y * __half2float(g1));
        atomicAdd(&d_agg3[dd0.z], w0.z * __half2float(g2));
        atomicAdd(&d_agg3[dd0.w], w0.w * __half2float(g3));
        atomicAdd(&d_agg3[dd1.x], w1.x * __half2float(g4));
        atomicAdd(&d_agg3[dd1.y], w1.y * __half2float(g5));
        atomicAdd(&d_agg3[dd1.z], w1.z * __half2float(g6));
        atomicAdd(&d_agg3[dd1.w], w1.w * __half2float(g7));
    }
}

// final: sigmoid(dinv*agg3*za + zc)
__global__ void k_out(float* __restrict__ out) {
    int i = blockIdx.x * blockDim.x + threadIdx.x;
    if (i < NN) {
        float z = fmaf(d_dinv[i] * d_agg3[i], d_za, d_zc);
        out[i] = 1.0f / (1.0f + __expf(-z));
    }
}

// ---------------- launch ----------------
extern "C" void kernel_launch(void* const* d_in, const int* in_sizes, int n_in,
                              void* d_out, int out_size) {
    const float* x   = (const float*)d_in[0];
    const int*   ei  = (const int*)d_in[1];      // int32 [2, E]
    const float* ew  = (const float*)d_in[2];
    const float* W1  = (const float*)d_in[3];
    const float* b1  = (const float*)d_in[4];
    const float* W2  = (const float*)d_in[5];
    const float* b2  = (const float*)d_in[6];
    const float* W3  = (const float*)d_in[7];
    const float* b3  = (const float*)d_in[8];
    const float* g1  = (const float*)d_in[9];
    const float* be1 = (const float*)d_in[10];
    const float* m1  = (const float*)d_in[11];
    const float* v1  = (const float*)d_in[12];
    const float* g2  = (const float*)d_in[13];
    const float* be2 = (const float*)d_in[14];
    const float* m2  = (const float*)d_in[15];
    const float* v2  = (const float*)d_in[16];
    const float* We  = (const float*)d_in[17];
    const float* bee = (const float*)d_in[18];

    const int TBN = 256;
    const int TBE = 128;                  // smaller blocks -> more blocks -> better balance
    const int NB_N  = NN / TBN;           // 1024
    const int NB_E8 = EE / 8 / TBE;       // 4096

    k_init<<<NB_N, TBN>>>(W1, b1, W2, b2, W3, b3, g1, be1, m1, v1, g2, be2, m2, v2, We, bee);
    k_deg<<<NB_E8, TBE>>>(ei, ew);
    k_dinv<<<NB_N, TBN>>>(x);
    k_e1<<<NB_E8, TBE>>>(ei, ew);
    k_n1<<<NB_N, TBN>>>();
    k_e2<<<NB_E8, TBE>>>(ei, ew);
    k_n2<<<NB_N, TBN>>>();
    k_e3<<<NB_E8, TBE>>>(ei, ew);
    k_out<<<NB_N, TBN>>>((float*)d_out);
}

// round 12
// speedup vs baseline: 1.0899x; 1.0057x over previous
#include <cuda_runtime.h>
#include <cuda_fp16.h>

// Problem-fixed shapes
#define NN 262144
#define EE 4194304
#define BN_EPS 1e-5f

// ---------------- scratch (static device globals; no allocation) ----------------
// d_deg is zero at module load and restored to zero by k_dinv every execution.
__device__ float  d_deg[NN];
__device__ float  d_dinv[NN];
__device__ __half d_gx[NN];       // f16: dinv[i] * x[i]          (512 KB)
__device__ float  d_agg1[NN];     // f32 accumulators
__device__ __half d_g2[NN * 4];   // f16 half4 per node           (2 MB)
__device__ float4 d_agg2[NN];
__device__ __half d_g3[NN];       // f16                          (512 KB)
__device__ float  d_agg3[NN];

// folded per-layer affine params
__device__ float d_a1[16], d_c1[16];   // layer1: relu(t*a1 + c1)
__device__ float d_W2v[64];            // [16,4] row-major
__device__ float d_s2[4], d_c2[4];     // layer2 bn fold
__device__ float d_W3v[4];
__device__ float d_za, d_zc;           // final: sigmoid(agg3*dinv*za + zc)

// 16B vector reduction (sm_90+)
__device__ __forceinline__ void red_add_v4(float4* addr, float a, float b, float c, float d) {
    asm volatile("red.global.add.v4.f32 [%0], {%1, %2, %3, %4};"
                 :: "l"(addr), "f"(a), "f"(b), "f"(c), "f"(d) : "memory");
}

// ---------------- kernels ----------------

// degree accumulation onto zeroed d_deg; block 0 also folds affine params
__global__ void k_deg(const int* __restrict__ ei, const float* __restrict__ ew,
                      const float* __restrict__ W1, const float* __restrict__ b1,
                      const float* __restrict__ W2, const float* __restrict__ b2,
                      const float* __restrict__ W3, const float* __restrict__ b3,
                      const float* __restrict__ g1, const float* __restrict__ be1,
                      const float* __restrict__ m1, const float* __restrict__ v1,
                      const float* __restrict__ g2, const float* __restrict__ be2,
                      const float* __restrict__ m2, const float* __restrict__ v2,
                      const float* __restrict__ We, const float* __restrict__ bee) {
    int t = blockIdx.x * blockDim.x + threadIdx.x;   // t < EE/8
    if (blockIdx.x == 0) {
        int u = threadIdx.x;
        if (u < 16) {
            float s = g1[u] * rsqrtf(v1[u] + BN_EPS);
            d_a1[u] = W1[u] * s;
            d_c1[u] = (b1[u] - m1[u]) * s + be1[u];
        }
        if (u < 64) d_W2v[u] = W2[u];
        if (u < 4) {
            float s = g2[u] * rsqrtf(v2[u] + BN_EPS);
            d_s2[u] = s;
            d_c2[u] = (b2[u] - m2[u]) * s + be2[u];
            d_W3v[u] = W3[u];
        }
        if (u == 0) { d_za = We[0]; d_zc = b3[0] * We[0] + bee[0]; }
    }
    if (t < EE / 8) {
        int4   dd0 = ((const int4*)(ei + EE))[2 * t + 0];
        int4   dd1 = ((const int4*)(ei + EE))[2 * t + 1];
        float4 w0  = ((const float4*)ew)[2 * t + 0];
        float4 w1  = ((const float4*)ew)[2 * t + 1];
        atomicAdd(&d_deg[dd0.x], w0.x);
        atomicAdd(&d_deg[dd0.y], w0.y);
        atomicAdd(&d_deg[dd0.z], w0.z);
        atomicAdd(&d_deg[dd0.w], w0.w);
        atomicAdd(&d_deg[dd1.x], w1.x);
        atomicAdd(&d_deg[dd1.y], w1.y);
        atomicAdd(&d_deg[dd1.z], w1.z);
        atomicAdd(&d_deg[dd1.w], w1.w);
    }
}

// vectorized x4: dinv = rsqrt(1+deg); gx = dinv*x (f16); agg1 init = gx; RESTORE deg=0
__global__ void k_dinv(const float* __restrict__ x) {
    int i = blockIdx.x * blockDim.x + threadIdx.x;   // i < NN/4
    if (i < NN / 4) {
        float4 dv = ((const float4*)d_deg)[i];
        float4 xv = ((const float4*)x)[i];
        float4 di;
        di.x = rsqrtf(1.0f + dv.x);
        di.y = rsqrtf(1.0f + dv.y);
        di.z = rsqrtf(1.0f + dv.z);
        di.w = rsqrtf(1.0f + dv.w);
        float4 g = make_float4(xv.x * di.x, xv.y * di.y, xv.z * di.z, xv.w * di.w);
        ((float4*)d_dinv)[i] = di;
        ((float4*)d_agg1)[i] = g;
        __half2 h01 = __floats2half2_rn(g.x, g.y);
        __half2 h23 = __floats2half2_rn(g.z, g.w);
        uint2 pk;
        pk.x = *(unsigned int*)&h01;
        pk.y = *(unsigned int*)&h23;
        ((uint2*)d_gx)[i] = pk;
        ((float4*)d_deg)[i] = make_float4(0.f, 0.f, 0.f, 0.f);  // restore invariant
    }
}

// edge pass 1: agg1[d] += w * gx[s]  — front-batch all 8 gathers, then 8 REDs
__global__ void k_e1(const int* __restrict__ ei, const float* __restrict__ ew) {
    int t = blockIdx.x * blockDim.x + threadIdx.x;   // t < EE/8
    if (t < EE / 8) {
        int4   ss0 = ((const int4*)ei)[2 * t + 0];
        int4   ss1 = ((const int4*)ei)[2 * t + 1];
        int4   dd0 = ((const int4*)(ei + EE))[2 * t + 0];
        int4   dd1 = ((const int4*)(ei + EE))[2 * t + 1];
        float4 w0  = ((const float4*)ew)[2 * t + 0];
        float4 w1  = ((const float4*)ew)[2 * t + 1];
        __half g0 = __ldg(&d_gx[ss0.x]);
        __half g1 = __ldg(&d_gx[ss0.y]);
        __half g2 = __ldg(&d_gx[ss0.z]);
        __half g3 = __ldg(&d_gx[ss0.w]);
        __half g4 = __ldg(&d_gx[ss1.x]);
        __half g5 = __ldg(&d_gx[ss1.y]);
        __half g6 = __ldg(&d_gx[ss1.z]);
        __half g7 = __ldg(&d_gx[ss1.w]);
        atomicAdd(&d_agg1[dd0.x], w0.x * __half2float(g0));
        atomicAdd(&d_agg1[dd0.y], w0.y * __half2float(g1));
        atomicAdd(&d_agg1[dd0.z], w0.z * __half2float(g2));
        atomicAdd(&d_agg1[dd0.w], w0.w * __half2float(g3));
        atomicAdd(&d_agg1[dd1.x], w1.x * __half2float(g4));
        atomicAdd(&d_agg1[dd1.y], w1.y * __half2float(g5));
        atomicAdd(&d_agg1[dd1.z], w1.z * __half2float(g6));
        atomicAdd(&d_agg1[dd1.w], w1.w * __half2float(g7));
    }
}

// node pass 1: t = dinv*agg1; folded bn+relu -> W2 -> h2; g2 = dinv*h2 (half4); agg2 init
__global__ void k_n1() {
    int i = blockIdx.x * blockDim.x + threadIdx.x;
    if (i < NN) {
        float di = d_dinv[i];
        float t = di * d_agg1[i];
        float a0 = 0.f, a1 = 0.f, a2 = 0.f, a3 = 0.f;
#pragma unroll
        for (int j = 0; j < 16; j++) {
            float p = fmaxf(fmaf(t, d_a1[j], d_c1[j]), 0.f);
            a0 = fmaf(p, d_W2v[j * 4 + 0], a0);
            a1 = fmaf(p, d_W2v[j * 4 + 1], a1);
            a2 = fmaf(p, d_W2v[j * 4 + 2], a2);
            a3 = fmaf(p, d_W2v[j * 4 + 3], a3);
        }
        float4 g = make_float4(a0 * di, a1 * di, a2 * di, a3 * di);
        __half2 h01 = __floats2half2_rn(g.x, g.y);
        __half2 h23 = __floats2half2_rn(g.z, g.w);
        uint2 pk;
        pk.x = *(unsigned int*)&h01;
        pk.y = *(unsigned int*)&h23;
        ((uint2*)d_g2)[i] = pk;
        d_agg2[i] = g;
    }
}

__device__ __forceinline__ float4 unpack_half4(uint2 pk) {
    __half2 h01 = *(__half2*)&pk.x;
    __half2 h23 = *(__half2*)&pk.y;
    float2 f01 = __half22float2(h01);
    float2 f23 = __half22float2(h23);
    return make_float4(f01.x, f01.y, f23.x, f23.y);
}

// edge pass 2: agg2[d] += w * g2[s]  — front-batch 8 gathers, then 8 v4 REDs
__global__ void k_e2(const int* __restrict__ ei, const float* __restrict__ ew) {
    int t = blockIdx.x * blockDim.x + threadIdx.x;   // t < EE/8
    if (t < EE / 8) {
        int4   ss0 = ((const int4*)ei)[2 * t + 0];
        int4   ss1 = ((const int4*)ei)[2 * t + 1];
        int4   dd0 = ((const int4*)(ei + EE))[2 * t + 0];
        int4   dd1 = ((const int4*)(ei + EE))[2 * t + 1];
        float4 w0  = ((const float4*)ew)[2 * t + 0];
        float4 w1  = ((const float4*)ew)[2 * t + 1];
        uint2 p0 = __ldg(&((const uint2*)d_g2)[ss0.x]);
        uint2 p1 = __ldg(&((const uint2*)d_g2)[ss0.y]);
        uint2 p2 = __ldg(&((const uint2*)d_g2)[ss0.z]);
        uint2 p3 = __ldg(&((const uint2*)d_g2)[ss0.w]);
        uint2 p4 = __ldg(&((const uint2*)d_g2)[ss1.x]);
        uint2 p5 = __ldg(&((const uint2*)d_g2)[ss1.y]);
        uint2 p6 = __ldg(&((const uint2*)d_g2)[ss1.z]);
        uint2 p7 = __ldg(&((const uint2*)d_g2)[ss1.w]);
        float4 h;
        h = unpack_half4(p0); red_add_v4(&d_agg2[dd0.x], w0.x*h.x, w0.x*h.y, w0.x*h.z, w0.x*h.w);
        h = unpack_half4(p1); red_add_v4(&d_agg2[dd0.y], w0.y*h.x, w0.y*h.y, w0.y*h.z, w0.y*h.w);
        h = unpack_half4(p2); red_add_v4(&d_agg2[dd0.z], w0.z*h.x, w0.z*h.y, w0.z*h.z, w0.z*h.w);
        h = unpack_half4(p3); red_add_v4(&d_agg2[dd0.w], w0.w*h.x, w0.w*h.y, w0.w*h.z, w0.w*h.w);
        h = unpack_half4(p4); red_add_v4(&d_agg2[dd1.x], w1.x*h.x, w1.x*h.y, w1.x*h.z, w1.x*h.w);
        h = unpack_half4(p5); red_add_v4(&d_agg2[dd1.y], w1.y*h.x, w1.y*h.y, w1.y*h.z, w1.y*h.w);
        h = unpack_half4(p6); red_add_v4(&d_agg2[dd1.z], w1.z*h.x, w1.z*h.y, w1.z*h.z, w1.z*h.w);
        h = unpack_half4(p7); red_add_v4(&d_agg2[dd1.w], w1.w*h.x, w1.w*h.y, w1.w*h.z, w1.w*h.w);
    }
}

// node pass 2: v = dinv*agg2; folded bn+relu -> W3 -> h3; g3 = dinv*h3 (f16); agg3 init
__global__ void k_n2() {
    int i = blockIdx.x * blockDim.x + threadIdx.x;
    if (i < NN) {
        float di = d_dinv[i];
        float4 v = d_agg2[i];
        float h3 = 0.f;
        float q;
        q = fmaxf(fmaf(di * v.x, d_s2[0], d_c2[0]), 0.f); h3 = fmaf(q, d_W3v[0], h3);
        q = fmaxf(fmaf(di * v.y, d_s2[1], d_c2[1]), 0.f); h3 = fmaf(q, d_W3v[1], h3);
        q = fmaxf(fmaf(di * v.z, d_s2[2], d_c2[2]), 0.f); h3 = fmaf(q, d_W3v[2], h3);
        q = fmaxf(fmaf(di * v.w, d_s2[3], d_c2[3]), 0.f); h3 = fmaf(q, d_W3v[3], h3);
        float g = h3 * di;
        d_g3[i] = __float2half(g);
        d_agg3[i] = g;
    }
}

// edge pass 3: agg3[d] += w * g3[s]  — front-batch gathers
__global__ void k_e3(const int* __restrict__ ei, const float* __restrict__ ew) {
    int t = blockIdx.x * blockDim.x + threadIdx.x;   // t < EE/8
    if (t < EE / 8) {
        int4   ss0 = ((const int4*)ei)[2 * t + 0];
        int4   ss1 = ((const int4*)ei)[2 * t + 1];
        int4   dd0 = ((const int4*)(ei + EE))[2 * t + 0];
        int4   dd1 = ((const int4*)(ei + EE))[2 * t + 1];
        float4 w0  = ((const float4*)ew)[2 * t + 0];
        float4 w1  = ((const float4*)ew)[2 * t + 1];
        __half g0 = __ldg(&d_g3[ss0.x]);
        __half g1 = __ldg(&d_g3[ss0.y]);
        __half g2 = __ldg(&d_g3[ss0.z]);
        __half g3 = __ldg(&d_g3[ss0.w]);
        __half g4 = __ldg(&d_g3[ss1.x]);
        __half g5 = __ldg(&d_g3[ss1.y]);
        __half g6 = __ldg(&d_g3[ss1.z]);
        __half g7 = __ldg(&d_g3[ss1.w]);
        atomicAdd(&d_agg3[dd0.x], w0.x * __half2float(g0));
        atomicAdd(&d_agg3[dd0.y], w0.y * __half2float(g1));
        atomicAdd(&d_agg3[dd0.z], w0.z * __half2float(g2));
        atomicAdd(&d_agg3[dd0.w], w0.w * __half2float(g3));
        atomicAdd(&d_agg3[dd1.x], w1.x * __half2float(g4));
        atomicAdd(&d_agg3[dd1.y], w1.y * __half2float(g5));
        atomicAdd(&d_agg3[dd1.z], w1.z * __half2float(g6));
        atomicAdd(&d_agg3[dd1.w], w1.w * __half2float(g7));
    }
}

// final (x4): sigmoid(dinv*agg3*za + zc)
__global__ void k_out(float* __restrict__ out) {
    int i = blockIdx.x * blockDim.x + threadIdx.x;   // i < NN/4
    if (i < NN / 4) {
        float4 di = ((const float4*)d_dinv)[i];
        float4 ag = ((const float4*)d_agg3)[i];
        float za = d_za, zc = d_zc;
        float4 o;
        o.x = 1.0f / (1.0f + __expf(-fmaf(di.x * ag.x, za, zc)));
        o.y = 1.0f / (1.0f + __expf(-fmaf(di.y * ag.y, za, zc)));
        o.z = 1.0f / (1.0f + __expf(-fmaf(di.z * ag.z, za, zc)));
        o.w = 1.0f / (1.0f + __expf(-fmaf(di.w * ag.w, za, zc)));
        ((float4*)out)[i] = o;
    }
}

// ---------------- launch ----------------
extern "C" void kernel_launch(void* const* d_in, const int* in_sizes, int n_in,
                              void* d_out, int out_size) {
    const float* x   = (const float*)d_in[0];
    const int*   ei  = (const int*)d_in[1];      // int32 [2, E]
    const float* ew  = (const float*)d_in[2];
    const float* W1  = (const float*)d_in[3];
    const float* b1  = (const float*)d_in[4];
    const float* W2  = (const float*)d_in[5];
    const float* b2  = (const float*)d_in[6];
    const float* W3  = (const float*)d_in[7];
    const float* b3  = (const float*)d_in[8];
    const float* g1  = (const float*)d_in[9];
    const float* be1 = (const float*)d_in[10];
    const float* m1  = (const float*)d_in[11];
    const float* v1  = (const float*)d_in[12];
    const float* g2  = (const float*)d_in[13];
    const float* be2 = (const float*)d_in[14];
    const float* m2  = (const float*)d_in[15];
    const float* v2  = (const float*)d_in[16];
    const float* We  = (const float*)d_in[17];
    const float* bee = (const float*)d_in[18];

    const int TBN = 256;
    const int TBE = 128;
    const int NB_N   = NN / TBN;          // 1024
    const int NB_N4  = NN / 4 / TBN;      // 256
    const int NB_E8  = EE / 8 / TBE;      // 4096

    k_deg<<<NB_E8, TBE>>>(ei, ew, W1, b1, W2, b2, W3, b3,
                          g1, be1, m1, v1, g2, be2, m2, v2, We, bee);
    k_dinv<<<NB_N4, TBN>>>(x);
    k_e1<<<NB_E8, TBE>>>(ei, ew);
    k_n1<<<NB_N, TBN>>>();
    k_e2<<<NB_E8, TBE>>>(ei, ew);
    k_n2<<<NB_N, TBN>>>();
    k_e3<<<NB_E8, TBE>>>(ei, ew);
    k_out<<<NB_N4, TBN>>>((float*)d_out);
}

// round 13
// speedup vs baseline: 1.1023x; 1.0114x over previous
#include <cuda_runtime.h>
#include <cuda_fp16.h>

// Problem-fixed shapes
#define NN 262144
#define EE 4194304
#define BN_EPS 1e-5f

// ---------------- scratch (static device globals; no allocation) ----------------
// d_deg is zero at module load and restored to zero by k_dinv every execution.
__device__ float  d_deg[NN];
__device__ float  d_dinv[NN];
__device__ __half d_gx[NN];       // f16: dinv[i] * x[i]          (512 KB)
__device__ float  d_agg1[NN];     // f32 accumulators
__device__ __half d_g2[NN * 4];   // f16 half4 per node           (2 MB)
__device__ float4 d_agg2[NN];
__device__ __half d_g3[NN];       // f16                          (512 KB)
__device__ float  d_agg3[NN];

// folded per-layer affine params
__device__ float d_a1[16], d_c1[16];   // layer1: relu(t*a1 + c1)
__device__ float d_W2v[64];            // [16,4] row-major
__device__ float d_s2[4], d_c2[4];     // layer2 bn fold
__device__ float d_W3v[4];
__device__ float d_za, d_zc;           // final: sigmoid(agg3*dinv*za + zc)

// 16B vector reduction (sm_90+)
__device__ __forceinline__ void red_add_v4(float4* addr, float a, float b, float c, float d) {
    asm volatile("red.global.add.v4.f32 [%0], {%1, %2, %3, %4};"
                 :: "l"(addr), "f"(a), "f"(b), "f"(c), "f"(d) : "memory");
}

// ---------------- kernels ----------------

// degree accumulation onto zeroed d_deg; block 0 also folds affine params
__global__ void k_deg(const int* __restrict__ ei, const float* __restrict__ ew,
                      const float* __restrict__ W1, const float* __restrict__ b1,
                      const float* __restrict__ W2, const float* __restrict__ b2,
                      const float* __restrict__ W3, const float* __restrict__ b3,
                      const float* __restrict__ g1, const float* __restrict__ be1,
                      const float* __restrict__ m1, const float* __restrict__ v1,
                      const float* __restrict__ g2, const float* __restrict__ be2,
                      const float* __restrict__ m2, const float* __restrict__ v2,
                      const float* __restrict__ We, const float* __restrict__ bee) {
    int t = blockIdx.x * blockDim.x + threadIdx.x;   // t < EE/8
    if (blockIdx.x == 0) {
        int u = threadIdx.x;
        if (u < 16) {
            float s = g1[u] * rsqrtf(v1[u] + BN_EPS);
            d_a1[u] = W1[u] * s;
            d_c1[u] = (b1[u] - m1[u]) * s + be1[u];
        }
        if (u < 64) d_W2v[u] = W2[u];
        if (u < 4) {
            float s = g2[u] * rsqrtf(v2[u] + BN_EPS);
            d_s2[u] = s;
            d_c2[u] = (b2[u] - m2[u]) * s + be2[u];
            d_W3v[u] = W3[u];
        }
        if (u == 0) { d_za = We[0]; d_zc = b3[0] * We[0] + bee[0]; }
    }
    if (t < EE / 8) {
        int4   dd0 = ((const int4*)(ei + EE))[2 * t + 0];
        int4   dd1 = ((const int4*)(ei + EE))[2 * t + 1];
        float4 w0  = ((const float4*)ew)[2 * t + 0];
        float4 w1  = ((const float4*)ew)[2 * t + 1];
        atomicAdd(&d_deg[dd0.x], w0.x);
        atomicAdd(&d_deg[dd0.y], w0.y);
        atomicAdd(&d_deg[dd0.z], w0.z);
        atomicAdd(&d_deg[dd0.w], w0.w);
        atomicAdd(&d_deg[dd1.x], w1.x);
        atomicAdd(&d_deg[dd1.y], w1.y);
        atomicAdd(&d_deg[dd1.z], w1.z);
        atomicAdd(&d_deg[dd1.w], w1.w);
    }
}

// vectorized x4: dinv = rsqrt(1+deg); gx = dinv*x (f16); agg1 init = gx; RESTORE deg=0
__global__ void k_dinv(const float* __restrict__ x) {
    int i = blockIdx.x * blockDim.x + threadIdx.x;   // i < NN/4
    if (i < NN / 4) {
        float4 dv = ((const float4*)d_deg)[i];
        float4 xv = ((const float4*)x)[i];
        float4 di;
        di.x = rsqrtf(1.0f + dv.x);
        di.y = rsqrtf(1.0f + dv.y);
        di.z = rsqrtf(1.0f + dv.z);
        di.w = rsqrtf(1.0f + dv.w);
        float4 g = make_float4(xv.x * di.x, xv.y * di.y, xv.z * di.z, xv.w * di.w);
        ((float4*)d_dinv)[i] = di;
        ((float4*)d_agg1)[i] = g;
        __half2 h01 = __floats2half2_rn(g.x, g.y);
        __half2 h23 = __floats2half2_rn(g.z, g.w);
        uint2 pk;
        pk.x = *(unsigned int*)&h01;
        pk.y = *(unsigned int*)&h23;
        ((uint2*)d_gx)[i] = pk;
        ((float4*)d_deg)[i] = make_float4(0.f, 0.f, 0.f, 0.f);  // restore invariant
    }
}

// edge pass 1: agg1[d] += w * gx[s]  — front-batch all 8 gathers, then 8 REDs
__global__ void k_e1(const int* __restrict__ ei, const float* __restrict__ ew) {
    int t = blockIdx.x * blockDim.x + threadIdx.x;   // t < EE/8
    if (t < EE / 8) {
        int4   ss0 = ((const int4*)ei)[2 * t + 0];
        int4   ss1 = ((const int4*)ei)[2 * t + 1];
        int4   dd0 = ((const int4*)(ei + EE))[2 * t + 0];
        int4   dd1 = ((const int4*)(ei + EE))[2 * t + 1];
        float4 w0  = ((const float4*)ew)[2 * t + 0];
        float4 w1  = ((const float4*)ew)[2 * t + 1];
        __half g0 = __ldg(&d_gx[ss0.x]);
        __half g1 = __ldg(&d_gx[ss0.y]);
        __half g2 = __ldg(&d_gx[ss0.z]);
        __half g3 = __ldg(&d_gx[ss0.w]);
        __half g4 = __ldg(&d_gx[ss1.x]);
        __half g5 = __ldg(&d_gx[ss1.y]);
        __half g6 = __ldg(&d_gx[ss1.z]);
        __half g7 = __ldg(&d_gx[ss1.w]);
        atomicAdd(&d_agg1[dd0.x], w0.x * __half2float(g0));
        atomicAdd(&d_agg1[dd0.y], w0.y * __half2float(g1));
        atomicAdd(&d_agg1[dd0.z], w0.z * __half2float(g2));
        atomicAdd(&d_agg1[dd0.w], w0.w * __half2float(g3));
        atomicAdd(&d_agg1[dd1.x], w1.x * __half2float(g4));
        atomicAdd(&d_agg1[dd1.y], w1.y * __half2float(g5));
        atomicAdd(&d_agg1[dd1.z], w1.z * __half2float(g6));
        atomicAdd(&d_agg1[dd1.w], w1.w * __half2float(g7));
    }
}

// node pass 1: params staged in SMEM (kills 96 LDG/thread -> LDS broadcast)
__global__ void k_n1() {
    __shared__ float sa1[16], sc1[16], sW2[64];
    int u = threadIdx.x;
    if (u < 16) { sa1[u] = d_a1[u]; sc1[u] = d_c1[u]; }
    if (u < 64) { sW2[u] = d_W2v[u]; }
    __syncthreads();
    int i = blockIdx.x * blockDim.x + u;
    if (i < NN) {
        float di = d_dinv[i];
        float t = di * d_agg1[i];
        float a0 = 0.f, a1 = 0.f, a2 = 0.f, a3 = 0.f;
#pragma unroll
        for (int j = 0; j < 16; j++) {
            float p = fmaxf(fmaf(t, sa1[j], sc1[j]), 0.f);
            a0 = fmaf(p, sW2[j * 4 + 0], a0);
            a1 = fmaf(p, sW2[j * 4 + 1], a1);
            a2 = fmaf(p, sW2[j * 4 + 2], a2);
            a3 = fmaf(p, sW2[j * 4 + 3], a3);
        }
        float4 g = make_float4(a0 * di, a1 * di, a2 * di, a3 * di);
        __half2 h01 = __floats2half2_rn(g.x, g.y);
        __half2 h23 = __floats2half2_rn(g.z, g.w);
        uint2 pk;
        pk.x = *(unsigned int*)&h01;
        pk.y = *(unsigned int*)&h23;
        ((uint2*)d_g2)[i] = pk;
        d_agg2[i] = g;
    }
}

__device__ __forceinline__ float4 unpack_half4(uint2 pk) {
    __half2 h01 = *(__half2*)&pk.x;
    __half2 h23 = *(__half2*)&pk.y;
    float2 f01 = __half22float2(h01);
    float2 f23 = __half22float2(h23);
    return make_float4(f01.x, f01.y, f23.x, f23.y);
}

// edge pass 2: agg2[d] += w * g2[s]  — front-batch 8 gathers, then 8 v4 REDs
__global__ void k_e2(const int* __restrict__ ei, const float* __restrict__ ew) {
    int t = blockIdx.x * blockDim.x + threadIdx.x;   // t < EE/8
    if (t < EE / 8) {
        int4   ss0 = ((const int4*)ei)[2 * t + 0];
        int4   ss1 = ((const int4*)ei)[2 * t + 1];
        int4   dd0 = ((const int4*)(ei + EE))[2 * t + 0];
        int4   dd1 = ((const int4*)(ei + EE))[2 * t + 1];
        float4 w0  = ((const float4*)ew)[2 * t + 0];
        float4 w1  = ((const float4*)ew)[2 * t + 1];
        uint2 p0 = __ldg(&((const uint2*)d_g2)[ss0.x]);
        uint2 p1 = __ldg(&((const uint2*)d_g2)[ss0.y]);
        uint2 p2 = __ldg(&((const uint2*)d_g2)[ss0.z]);
        uint2 p3 = __ldg(&((const uint2*)d_g2)[ss0.w]);
        uint2 p4 = __ldg(&((const uint2*)d_g2)[ss1.x]);
        uint2 p5 = __ldg(&((const uint2*)d_g2)[ss1.y]);
        uint2 p6 = __ldg(&((const uint2*)d_g2)[ss1.z]);
        uint2 p7 = __ldg(&((const uint2*)d_g2)[ss1.w]);
        float4 h;
        h = unpack_half4(p0); red_add_v4(&d_agg2[dd0.x], w0.x*h.x, w0.x*h.y, w0.x*h.z, w0.x*h.w);
        h = unpack_half4(p1); red_add_v4(&d_agg2[dd0.y], w0.y*h.x, w0.y*h.y, w0.y*h.z, w0.y*h.w);
        h = unpack_half4(p2); red_add_v4(&d_agg2[dd0.z], w0.z*h.x, w0.z*h.y, w0.z*h.z, w0.z*h.w);
        h = unpack_half4(p3); red_add_v4(&d_agg2[dd0.w], w0.w*h.x, w0.w*h.y, w0.w*h.z, w0.w*h.w);
        h = unpack_half4(p4); red_add_v4(&d_agg2[dd1.x], w1.x*h.x, w1.x*h.y, w1.x*h.z, w1.x*h.w);
        h = unpack_half4(p5); red_add_v4(&d_agg2[dd1.y], w1.y*h.x, w1.y*h.y, w1.y*h.z, w1.y*h.w);
        h = unpack_half4(p6); red_add_v4(&d_agg2[dd1.z], w1.z*h.x, w1.z*h.y, w1.z*h.z, w1.z*h.w);
        h = unpack_half4(p7); red_add_v4(&d_agg2[dd1.w], w1.w*h.x, w1.w*h.y, w1.w*h.z, w1.w*h.w);
    }
}

// node pass 2: params staged in SMEM; v = dinv*agg2; bn+relu -> W3 -> g3; agg3 init
__global__ void k_n2() {
    __shared__ float ss2[4], sc2[4], sW3[4];
    int u = threadIdx.x;
    if (u < 4) { ss2[u] = d_s2[u]; sc2[u] = d_c2[u]; sW3[u] = d_W3v[u]; }
    __syncthreads();
    int i = blockIdx.x * blockDim.x + u;
    if (i < NN) {
        float di = d_dinv[i];
        float4 v = d_agg2[i];
        float h3 = 0.f;
        float q;
        q = fmaxf(fmaf(di * v.x, ss2[0], sc2[0]), 0.f); h3 = fmaf(q, sW3[0], h3);
        q = fmaxf(fmaf(di * v.y, ss2[1], sc2[1]), 0.f); h3 = fmaf(q, sW3[1], h3);
        q = fmaxf(fmaf(di * v.z, ss2[2], sc2[2]), 0.f); h3 = fmaf(q, sW3[2], h3);
        q = fmaxf(fmaf(di * v.w, ss2[3], sc2[3]), 0.f); h3 = fmaf(q, sW3[3], h3);
        float g = h3 * di;
        d_g3[i] = __float2half(g);
        d_agg3[i] = g;
    }
}

// edge pass 3: agg3[d] += w * g3[s]  — front-batch gathers
__global__ void k_e3(const int* __restrict__ ei, const float* __restrict__ ew) {
    int t = blockIdx.x * blockDim.x + threadIdx.x;   // t < EE/8
    if (t < EE / 8) {
        int4   ss0 = ((const int4*)ei)[2 * t + 0];
        int4   ss1 = ((const int4*)ei)[2 * t + 1];
        int4   dd0 = ((const int4*)(ei + EE))[2 * t + 0];
        int4   dd1 = ((const int4*)(ei + EE))[2 * t + 1];
        float4 w0  = ((const float4*)ew)[2 * t + 0];
        float4 w1  = ((const float4*)ew)[2 * t + 1];
        __half g0 = __ldg(&d_g3[ss0.x]);
        __half g1 = __ldg(&d_g3[ss0.y]);
        __half g2 = __ldg(&d_g3[ss0.z]);
        __half g3 = __ldg(&d_g3[ss0.w]);
        __half g4 = __ldg(&d_g3[ss1.x]);
        __half g5 = __ldg(&d_g3[ss1.y]);
        __half g6 = __ldg(&d_g3[ss1.z]);
        __half g7 = __ldg(&d_g3[ss1.w]);
        atomicAdd(&d_agg3[dd0.x], w0.x * __half2float(g0));
        atomicAdd(&d_agg3[dd0.y], w0.y * __half2float(g1));
        atomicAdd(&d_agg3[dd0.z], w0.z * __half2float(g2));
        atomicAdd(&d_agg3[dd0.w], w0.w * __half2float(g3));
        atomicAdd(&d_agg3[dd1.x], w1.x * __half2float(g4));
        atomicAdd(&d_agg3[dd1.y], w1.y * __half2float(g5));
        atomicAdd(&d_agg3[dd1.z], w1.z * __half2float(g6));
        atomicAdd(&d_agg3[dd1.w], w1.w * __half2float(g7));
    }
}

// final (x4): sigmoid(dinv*agg3*za + zc)
__global__ void k_out(float* __restrict__ out) {
    int i = blockIdx.x * blockDim.x + threadIdx.x;   // i < NN/4
    if (i < NN / 4) {
        float4 di = ((const float4*)d_dinv)[i];
        float4 ag = ((const float4*)d_agg3)[i];
        float za = d_za, zc = d_zc;
        float4 o;
        o.x = 1.0f / (1.0f + __expf(-fmaf(di.x * ag.x, za, zc)));
        o.y = 1.0f / (1.0f + __expf(-fmaf(di.y * ag.y, za, zc)));
        o.z = 1.0f / (1.0f + __expf(-fmaf(di.z * ag.z, za, zc)));
        o.w = 1.0f / (1.0f + __expf(-fmaf(di.w * ag.w, za, zc)));
        ((float4*)out)[i] = o;
    }
}

// ---------------- launch ----------------
extern "C" void kernel_launch(void* const* d_in, const int* in_sizes, int n_in,
                              void* d_out, int out_size) {
    const float* x   = (const float*)d_in[0];
    const int*   ei  = (const int*)d_in[1];      // int32 [2, E]
    const float* ew  = (const float*)d_in[2];
    const float* W1  = (const float*)d_in[3];
    const float* b1  = (const float*)d_in[4];
    const float* W2  = (const float*)d_in[5];
    const float* b2  = (const float*)d_in[6];
    const float* W3  = (const float*)d_in[7];
    const float* b3  = (const float*)d_in[8];
    const float* g1  = (const float*)d_in[9];
    const float* be1 = (const float*)d_in[10];
    const float* m1  = (const float*)d_in[11];
    const float* v1  = (const float*)d_in[12];
    const float* g2  = (const float*)d_in[13];
    const float* be2 = (const float*)d_in[14];
    const float* m2  = (const float*)d_in[15];
    const float* v2  = (const float*)d_in[16];
    const float* We  = (const float*)d_in[17];
    const float* bee = (const float*)d_in[18];

    const int TBN = 256;
    const int TBE = 128;
    const int NB_N   = NN / TBN;          // 1024
    const int NB_N4  = NN / 4 / TBN;      // 256
    const int NB_E8  = EE / 8 / TBE;      // 4096

    k_deg<<<NB_E8, TBE>>>(ei, ew, W1, b1, W2, b2, W3, b3,
                          g1, be1, m1, v1, g2, be2, m2, v2, We, bee);
    k_dinv<<<NB_N4, TBN>>>(x);
    k_e1<<<NB_E8, TBE>>>(ei, ew);
    k_n1<<<NB_N, TBN>>>();
    k_e2<<<NB_E8, TBE>>>(ei, ew);
    k_n2<<<NB_N, TBN>>>();
    k_e3<<<NB_E8, TBE>>>(ei, ew);
    k_out<<<NB_N4, TBN>>>((float*)d_out);
}